// round 8
// baseline (speedup 1.0000x reference)
#include <cuda_runtime.h>
#include <math.h>

#define MREL 8
#define DDIM 256
#define MAXN 51200

typedef unsigned int u32;

// ---------------- scratch (no cudaMalloc allowed) ----------------
__device__ float g_zsum[(size_t)MAXN * DDIM];        // fp32 (unrounded)
__device__ float g_zmax[(size_t)MAXN * DDIM];        // fp32
__device__ float g_zagr[(size_t)MAXN * DDIM];        // fp32
__device__ float g_zpre[(size_t)MAXN * DDIM];        // fp32
__device__ float g_wT[16 * 256 * 256];               // [m*2+mat][e][k] K-major, rna-tf32
__device__ float g_wcT[256 * 768];                   // [e][k] K-major, rna-tf32

__device__ __forceinline__ u32 f2tf(float x) {       // round-to-nearest tf32
    u32 r; asm("cvt.rna.tf32.f32 %0, %1;" : "=r"(r) : "f"(x)); return r;
}
__device__ __forceinline__ float tfbits(float x) { return __uint_as_float(f2tf(x)); }
__device__ __forceinline__ u32 fasu(float x) { return __float_as_uint(x); }

__device__ __forceinline__ void mma8(float* d, const u32* a, const u32* b) {
    asm volatile(
        "mma.sync.aligned.m16n8k8.row.col.f32.tf32.tf32.f32 "
        "{%0,%1,%2,%3}, {%4,%5,%6,%7}, {%8,%9}, {%0,%1,%2,%3};"
        : "+f"(d[0]), "+f"(d[1]), "+f"(d[2]), "+f"(d[3])
        : "r"(a[0]), "r"(a[1]), "r"(a[2]), "r"(a[3]), "r"(b[0]), "r"(b[1]));
}
__device__ __forceinline__ void cpa16(u32 dst, const void* src) {
    asm volatile("cp.async.cg.shared.global [%0], [%1], 16;" :: "r"(dst), "l"(src));
}
#define CP_COMMIT() asm volatile("cp.async.commit_group;")
#define CP_WAIT1()  asm volatile("cp.async.wait_group 1;")

// ============================================================================
// Weight transposes (rna-tf32 outputs)
// ============================================================================
__global__ void k_wtrans(const float* __restrict__ Wmax, const float* __restrict__ Wphi) {
    __shared__ float t[32][33];
    int z = blockIdx.z;
    const float* src = ((z & 1) ? Wphi : Wmax) + (size_t)(z >> 1) * 65536;
    float* dst = g_wT + (size_t)z * 65536;
    int e0 = blockIdx.x * 32, k0 = blockIdx.y * 32;
    int tx = threadIdx.x & 31, ty = threadIdx.x >> 5;
#pragma unroll
    for (int i = 0; i < 4; i++) t[ty + i * 8][tx] = src[(size_t)(k0 + ty + i * 8) * 256 + e0 + tx];
    __syncthreads();
#pragma unroll
    for (int i = 0; i < 4; i++)
        dst[(size_t)(e0 + ty + i * 8) * 256 + k0 + tx] = tfbits(t[tx][ty + i * 8]);
}
__global__ void k_wctrans(const float* __restrict__ Wc) {
    __shared__ float t[32][33];
    int k0 = blockIdx.x * 32, e0 = blockIdx.y * 32;
    int tx = threadIdx.x & 31, ty = threadIdx.x >> 5;
#pragma unroll
    for (int i = 0; i < 4; i++) t[ty + i * 8][tx] = Wc[(size_t)(k0 + ty + i * 8) * 256 + e0 + tx];
    __syncthreads();
#pragma unroll
    for (int i = 0; i < 4; i++)
        g_wcT[(size_t)(e0 + ty + i * 8) * 768 + k0 + tx] = tfbits(t[tx][ty + i * 8]);
}

// ============================================================================
// Kernel 1: gate softmax + z_sum (fp32 out). One warp per node.
// ============================================================================
__global__ void k_gate_zsum(const float* __restrict__ zs, const float* __restrict__ Wb,
                            const float* __restrict__ bb, int N) {
    extern __shared__ float swb[];  // 2048 * 9
    int tid = threadIdx.x;
    for (int e = tid; e < 2048 * 8; e += blockDim.x)
        swb[(e >> 3) * 9 + (e & 7)] = Wb[e];
    __syncthreads();

    int lane = tid & 31, wid = tid >> 5;
    int wpb = blockDim.x >> 5, stride = wpb * gridDim.x;
    float bbv[8];
#pragma unroll
    for (int j = 0; j < 8; j++) bbv[j] = bb[j];

    for (int n = blockIdx.x * wpb + wid; n < N; n += stride) {
        float vals[MREL][8];
#pragma unroll
        for (int m = 0; m < MREL; m++) {
            const float* p = zs + ((size_t)m * N + n) * DDIM + lane;
#pragma unroll
            for (int i = 0; i < 8; i++) vals[m][i] = p[32 * i];
        }
        float lg[8] = {0.f,0.f,0.f,0.f,0.f,0.f,0.f,0.f};
#pragma unroll
        for (int m = 0; m < MREL; m++) {
#pragma unroll
            for (int i = 0; i < 8; i++) {
                const float* w = swb + (size_t)(m * DDIM + lane + 32 * i) * 9;
                float v = vals[m][i];
#pragma unroll
                for (int j = 0; j < 8; j++) lg[j] = fmaf(v, w[j], lg[j]);
            }
        }
#pragma unroll
        for (int off = 16; off > 0; off >>= 1) {
#pragma unroll
            for (int j = 0; j < 8; j++) lg[j] += __shfl_xor_sync(0xffffffffu, lg[j], off);
        }
        float mx = -1e30f;
#pragma unroll
        for (int j = 0; j < 8; j++) { lg[j] += bbv[j]; mx = fmaxf(mx, lg[j]); }
        float g[8], se = 0.f;
#pragma unroll
        for (int j = 0; j < 8; j++) { g[j] = expf(lg[j] - mx); se += g[j]; }
        float inv = 1.f / se;
        float* q = g_zsum + (size_t)n * DDIM + lane;
#pragma unroll
        for (int i = 0; i < 8; i++) {
            float a = 0.f;
#pragma unroll
            for (int m = 0; m < MREL; m++) a = fmaf(g[m], vals[m][i], a);
            q[32 * i] = a * inv;
        }
    }
}

// ============================================================================
// Kernel 2: fused dual-GEMM + fold. CTA tile 128 nodes x 64 e-cols, proj+phi
// per warp. K-chunk 64, 3-stage cp.async, prefetch distance 2, wait_group 1.
// smem: biases 4096 | A 3 x 34816 | B 3 x 34816 = 212992 B (1 CTA/SM).
// ============================================================================
__global__ void __launch_bounds__(256, 1) k_maxphi_mma(
        const float* __restrict__ zs,
        const float* __restrict__ bmax, const float* __restrict__ bphi, int N) {
    extern __shared__ float sh[];
    u32 shb = (u32)__cvta_generic_to_shared(sh);
    float* sbm = sh;                    // [8][64]
    float* sbp = sh + 512;              // [8][64]
    float* sAf = sh + 1024;             // 3 x [128][68]
    float* sBf = sh + 1024 + 3 * 8704;  // 3 x [128][68] (rows 0-63 proj, 64-127 phi)
    const u32 A0 = shb + 4096, B0 = shb + 4096 + 3 * 34816;

    int tid = threadIdx.x, wid = tid >> 5, lane = tid & 31;
    int g = lane >> 2, t4 = lane & 3;
    int warpM = wid & 3, warpN = wid >> 2;
    int e0 = blockIdx.x * 64, n0 = blockIdx.y * 128;

    for (int i = tid; i < MREL * 64; i += 256) {
        int m = i >> 6, c = i & 63;
        sbm[i] = bmax[m * DDIM + e0 + c];
        sbp[i] = bphi[m * DDIM + e0 + c];
    }

    auto stage = [&](int it) {
        int m = it >> 2, k0 = (it & 3) * 64, s = it % 3;
        const float* za = zs + (size_t)m * N * DDIM;
        const float* wb = g_wT + (size_t)m * 2 * 65536;
        u32 sa = A0 + s * 34816, sb = B0 + s * 34816;
#pragma unroll
        for (int j = 0; j < 8; j++) {
            int f = tid + j * 256;             // A: 2048 16B chunks
            int row = f >> 4, kq = f & 15;
            int nr = n0 + row; if (nr >= N) nr = N - 1;
            cpa16(sa + row * 272 + kq * 16, za + (size_t)nr * DDIM + k0 + kq * 4);
        }
#pragma unroll
        for (int j = 0; j < 8; j++) {
            int f = tid + j * 256;             // B: 2048 16B chunks
            int row = f >> 4, kq = f & 15;
            const float* src = wb + (row >= 64 ? 65536 : 0)
                               + (size_t)(e0 + (row & 63)) * 256 + k0 + kq * 4;
            cpa16(sb + row * 272 + kq * 16, src);
        }
    };

    stage(0); CP_COMMIT();
    stage(1); CP_COMMIT();

    float stP[32], stF1[32], stF2[32];
#pragma unroll
    for (int i = 0; i < 32; i++) { stP[i] = -3.0e38f; stF1[i] = 0.f; stF2[i] = 0.f; }

    float dP[2][4][4], dF[2][4][4];

    for (int it = 0; it < 32; it++) {
        int m = it >> 2, chunk = it & 3, s = it % 3;
        if (chunk == 0) {
#pragma unroll
            for (int mm = 0; mm < 2; mm++)
#pragma unroll
                for (int nn = 0; nn < 4; nn++)
#pragma unroll
                    for (int i = 0; i < 4; i++) { dP[mm][nn][i] = 0.f; dF[mm][nn][i] = 0.f; }
        }
        CP_WAIT1();                // group 'it' done; 'it+1' may still fly
        __syncthreads();           // also orders last read of buffer (it+2)%3
        if (it + 2 < 32) { stage(it + 2); CP_COMMIT(); }

        const float* A  = sAf + s * 8704 + (warpM * 32 + g) * 68;
        const float* Bp = sBf + s * 8704 + (warpN * 32 + g) * 68;
        const float* Bf = Bp + 64 * 68;
#pragma unroll
        for (int ks = 0; ks < 8; ks++) {
            int kb = ks * 8 + t4;
            u32 a[2][4], bp[4][2], bf[4][2];
#pragma unroll
            for (int mm = 0; mm < 2; mm++) {
                const float* ar = A + mm * 16 * 68 + kb;
                a[mm][0] = f2tf(ar[0]);
                a[mm][1] = f2tf(ar[8 * 68]);
                a[mm][2] = f2tf(ar[4]);
                a[mm][3] = f2tf(ar[8 * 68 + 4]);
            }
#pragma unroll
            for (int nn = 0; nn < 4; nn++) {
                const float* bpr = Bp + nn * 8 * 68 + kb;
                bp[nn][0] = fasu(bpr[0]); bp[nn][1] = fasu(bpr[4]);
                const float* bfr = Bf + nn * 8 * 68 + kb;
                bf[nn][0] = fasu(bfr[0]); bf[nn][1] = fasu(bfr[4]);
            }
#pragma unroll
            for (int mm = 0; mm < 2; mm++)
#pragma unroll
                for (int nn = 0; nn < 4; nn++) {
                    mma8(dP[mm][nn], a[mm], bp[nn]);
                    mma8(dF[mm][nn], a[mm], bf[nn]);
                }
        }

        if (chunk == 3) {  // fold relation m
#pragma unroll
            for (int nn = 0; nn < 4; nn++) {
                int cb = m * 64 + warpN * 32 + nn * 8 + t4 * 2;
                float bm0 = sbm[cb], bm1 = sbm[cb + 1];
                float bp0 = sbp[cb], bp1 = sbp[cb + 1];
#pragma unroll
                for (int mm = 0; mm < 2; mm++) {
                    int ix = mm * 16 + nn * 4;
                    stP[ix + 0] = fmaxf(stP[ix + 0], dP[mm][nn][0] + bm0);
                    stP[ix + 1] = fmaxf(stP[ix + 1], dP[mm][nn][1] + bm1);
                    stP[ix + 2] = fmaxf(stP[ix + 2], dP[mm][nn][2] + bm0);
                    stP[ix + 3] = fmaxf(stP[ix + 3], dP[mm][nn][3] + bm1);
                    float v0 = dF[mm][nn][0] + bp0, v1 = dF[mm][nn][1] + bp1;
                    float v2 = dF[mm][nn][2] + bp0, v3 = dF[mm][nn][3] + bp1;
                    stF1[ix + 0] += v0; stF2[ix + 0] = fmaf(v0, v0, stF2[ix + 0]);
                    stF1[ix + 1] += v1; stF2[ix + 1] = fmaf(v1, v1, stF2[ix + 1]);
                    stF1[ix + 2] += v2; stF2[ix + 2] = fmaf(v2, v2, stF2[ix + 2]);
                    stF1[ix + 3] += v3; stF2[ix + 3] = fmaf(v3, v3, stF2[ix + 3]);
                }
            }
        }
    }

#pragma unroll
    for (int mm = 0; mm < 2; mm++) {
#pragma unroll
        for (int h = 0; h < 2; h++) {
            int n = n0 + warpM * 32 + mm * 16 + g + h * 8;
            if (n >= N) continue;
#pragma unroll
            for (int nn = 0; nn < 4; nn++) {
                int ix = mm * 16 + nn * 4 + h * 2;
                int e = e0 + warpN * 32 + nn * 8 + t4 * 2;
                *(float2*)(g_zmax + (size_t)n * DDIM + e) = make_float2(stP[ix], stP[ix + 1]);
                float a0 = 0.5f * (stF1[ix] * stF1[ix] - stF2[ix]);
                float a1 = 0.5f * (stF1[ix + 1] * stF1[ix + 1] - stF2[ix + 1]);
                *(float2*)(g_zagr + (size_t)n * DDIM + e) = make_float2(a0, a1);
            }
        }
    }
}

// ============================================================================
// Kernel 3: combine GEMM (K=768), A-side hi/lo split (2 mmas).
// K-chunk 64, 3-stage cp.async distance 2. CTA 128 x 64; warps 4M x 2N.
// smem: A 3 x 34816 | B 3 x 17408 = 156672 B (1 CTA/SM).
// ============================================================================
__global__ void __launch_bounds__(256, 1) k_combine_mma(
        const float* __restrict__ bc, int N) {
    extern __shared__ float sh[];
    u32 shb = (u32)__cvta_generic_to_shared(sh);
    float* sAf = sh;                 // 3 x [128][68]
    float* sBf = sh + 3 * 8704;      // 3 x [64][68]
    const u32 A0 = shb, B0 = shb + 3 * 34816;

    int tid = threadIdx.x, wid = tid >> 5, lane = tid & 31;
    int g = lane >> 2, t4 = lane & 3;
    int warpM = wid & 3, warpN = wid >> 2;
    int e0 = blockIdx.x * 64, n0 = blockIdx.y * 128;

    auto stage = [&](int c) {
        int k0 = c * 64, s = c % 3;
        const float* src = (k0 < 256) ? g_zsum : (k0 < 512) ? g_zmax : g_zagr;
        int kc = k0 & 255;
        u32 sa = A0 + s * 34816, sb = B0 + s * 17408;
#pragma unroll
        for (int j = 0; j < 8; j++) {
            int f = tid + j * 256;           // A: 2048 chunks
            int row = f >> 4, kq = f & 15;
            int nr = n0 + row; if (nr >= N) nr = N - 1;
            cpa16(sa + row * 272 + kq * 16, src + (size_t)nr * DDIM + kc + kq * 4);
        }
#pragma unroll
        for (int j = 0; j < 4; j++) {
            int f = tid + j * 256;           // B: 1024 chunks
            int row = f >> 4, kq = f & 15;
            cpa16(sb + row * 272 + kq * 16, g_wcT + (size_t)(e0 + row) * 768 + k0 + kq * 4);
        }
    };

    stage(0); CP_COMMIT();
    stage(1); CP_COMMIT();

    float d[2][4][4];
#pragma unroll
    for (int mm = 0; mm < 2; mm++)
#pragma unroll
        for (int nn = 0; nn < 4; nn++)
#pragma unroll
            for (int i = 0; i < 4; i++) d[mm][nn][i] = 0.f;

    for (int c = 0; c < 12; c++) {
        int s = c % 3;
        CP_WAIT1();
        __syncthreads();
        if (c + 2 < 12) { stage(c + 2); CP_COMMIT(); }

        const float* A = sAf + s * 8704 + (warpM * 32 + g) * 68;
        const float* B = sBf + s * 4352 + (warpN * 32 + g) * 68;
#pragma unroll
        for (int ks = 0; ks < 8; ks++) {
            int kb = ks * 8 + t4;
            u32 ahi[2][4], alo[2][4], b[4][2];
#pragma unroll
            for (int mm = 0; mm < 2; mm++) {
                const float* ar = A + mm * 16 * 68 + kb;
                float r0 = ar[0], r1 = ar[8 * 68], r2 = ar[4], r3 = ar[8 * 68 + 4];
                ahi[mm][0] = f2tf(r0); alo[mm][0] = fasu(r0 - __uint_as_float(ahi[mm][0]));
                ahi[mm][1] = f2tf(r1); alo[mm][1] = fasu(r1 - __uint_as_float(ahi[mm][1]));
                ahi[mm][2] = f2tf(r2); alo[mm][2] = fasu(r2 - __uint_as_float(ahi[mm][2]));
                ahi[mm][3] = f2tf(r3); alo[mm][3] = fasu(r3 - __uint_as_float(ahi[mm][3]));
            }
#pragma unroll
            for (int nn = 0; nn < 4; nn++) {
                const float* br = B + nn * 8 * 68 + kb;
                b[nn][0] = fasu(br[0]); b[nn][1] = fasu(br[4]);
            }
#pragma unroll
            for (int mm = 0; mm < 2; mm++)
#pragma unroll
                for (int nn = 0; nn < 4; nn++) {
                    mma8(d[mm][nn], alo[mm], b[nn]);
                    mma8(d[mm][nn], ahi[mm], b[nn]);
                }
        }
    }

#pragma unroll
    for (int mm = 0; mm < 2; mm++) {
#pragma unroll
        for (int h = 0; h < 2; h++) {
            int n = n0 + warpM * 32 + mm * 16 + g + h * 8;
            if (n >= N) continue;
#pragma unroll
            for (int nn = 0; nn < 4; nn++) {
                int e = e0 + warpN * 32 + nn * 8 + t4 * 2;
                float b0 = __ldg(bc + e), b1 = __ldg(bc + e + 1);
                *(float2*)(g_zpre + (size_t)n * DDIM + e) =
                    make_float2(d[mm][nn][h * 2] + b0, d[mm][nn][h * 2 + 1] + b1);
            }
        }
    }
}

// ============================================================================
// Kernel 4: LayerNorm. One warp per node.
// ============================================================================
__global__ void k_ln(const float* __restrict__ gamma, const float* __restrict__ beta,
                     float* __restrict__ out, int N) {
    int tid = threadIdx.x;
    int lane = tid & 31, wid = tid >> 5;
    int n = blockIdx.x * (blockDim.x >> 5) + wid;
    if (n >= N) return;

    const float* p = g_zpre + (size_t)n * DDIM + lane * 8;
    float4 v0 = *(const float4*)p;
    float4 v1 = *(const float4*)(p + 4);
    float v[8] = {v0.x, v0.y, v0.z, v0.w, v1.x, v1.y, v1.z, v1.w};
    float s = 0.f, q = 0.f;
#pragma unroll
    for (int dd = 0; dd < 8; dd++) { s += v[dd]; q = fmaf(v[dd], v[dd], q); }
#pragma unroll
    for (int off = 16; off > 0; off >>= 1) {
        s += __shfl_xor_sync(0xffffffffu, s, off);
        q += __shfl_xor_sync(0xffffffffu, q, off);
    }
    float mean = s * (1.f / 256.f);
    float var = q * (1.f / 256.f) - mean * mean;
    float inv = rsqrtf(var + 1e-5f);

    const float* gp = gamma + lane * 8;
    const float* bp = beta + lane * 8;
    float4 g0 = *(const float4*)gp, g1 = *(const float4*)(gp + 4);
    float4 b0 = *(const float4*)bp, b1 = *(const float4*)(bp + 4);
    float gg[8] = {g0.x, g0.y, g0.z, g0.w, g1.x, g1.y, g1.z, g1.w};
    float bbv[8] = {b0.x, b0.y, b0.z, b0.w, b1.x, b1.y, b1.z, b1.w};
    float o[8];
#pragma unroll
    for (int dd = 0; dd < 8; dd++) o[dd] = fmaf((v[dd] - mean) * inv, gg[dd], bbv[dd]);

    float* qo = out + (size_t)n * DDIM + lane * 8;
    *(float4*)qo       = make_float4(o[0], o[1], o[2], o[3]);
    *(float4*)(qo + 4) = make_float4(o[4], o[5], o[6], o[7]);
}

// ============================================================================
extern "C" void kernel_launch(void* const* d_in, const int* in_sizes, int n_in,
                              void* d_out, int out_size) {
    const float* zs    = (const float*)d_in[0];
    const float* Wb    = (const float*)d_in[1];
    const float* bb    = (const float*)d_in[2];
    const float* Wmax  = (const float*)d_in[3];
    const float* bmax  = (const float*)d_in[4];
    const float* Wphi  = (const float*)d_in[5];
    const float* bphi  = (const float*)d_in[6];
    const float* Wc    = (const float*)d_in[7];
    const float* bc    = (const float*)d_in[8];
    const float* gamma = (const float*)d_in[9];
    const float* beta  = (const float*)d_in[10];
    float* out = (float*)d_out;

    int N = in_sizes[0] / (MREL * DDIM);
    int nt128 = (N + 127) / 128;

    cudaFuncSetAttribute(k_gate_zsum, cudaFuncAttributeMaxDynamicSharedMemorySize, 73728);
    cudaFuncSetAttribute(k_maxphi_mma, cudaFuncAttributeMaxDynamicSharedMemorySize, 212992);
    cudaFuncSetAttribute(k_combine_mma, cudaFuncAttributeMaxDynamicSharedMemorySize, 156672);

    k_wtrans<<<dim3(8, 8, 16), 256>>>(Wmax, Wphi);
    k_wctrans<<<dim3(24, 8), 256>>>(Wc);

    k_gate_zsum<<<592, 256, 73728>>>(zs, Wb, bb, N);

    k_maxphi_mma<<<dim3(4, nt128), 256, 212992>>>(zs, bmax, bphi, N);

    k_combine_mma<<<dim3(4, nt128), 256, 156672>>>(bc, N);

    k_ln<<<(N + 7) / 8, 256>>>(gamma, beta, out, N);
}

// round 9
// speedup vs baseline: 1.0558x; 1.0558x over previous
#include <cuda_runtime.h>
#include <math.h>

#define MREL 8
#define DDIM 256
#define MAXN 51200

typedef unsigned int u32;

// ---------------- scratch (no cudaMalloc allowed) ----------------
__device__ float g_zsum[(size_t)MAXN * DDIM];        // fp32 (unrounded)
__device__ float g_zmax[(size_t)MAXN * DDIM];        // fp32
__device__ float g_zagr[(size_t)MAXN * DDIM];        // fp32
__device__ float g_zpre[(size_t)MAXN * DDIM];        // fp32
__device__ float g_wT[16 * 256 * 256];               // [m*2+mat][e][k] K-major, rna-tf32
__device__ float g_wcT[256 * 768];                   // [e][k] K-major, rna-tf32

__device__ __forceinline__ u32 f2tf(float x) {       // round-to-nearest tf32
    u32 r; asm("cvt.rna.tf32.f32 %0, %1;" : "=r"(r) : "f"(x)); return r;
}
__device__ __forceinline__ float tfbits(float x) { return __uint_as_float(f2tf(x)); }
__device__ __forceinline__ u32 fasu(float x) { return __float_as_uint(x); }

__device__ __forceinline__ void mma8(float* d, const u32* a, const u32* b) {
    asm volatile(
        "mma.sync.aligned.m16n8k8.row.col.f32.tf32.tf32.f32 "
        "{%0,%1,%2,%3}, {%4,%5,%6,%7}, {%8,%9}, {%0,%1,%2,%3};"
        : "+f"(d[0]), "+f"(d[1]), "+f"(d[2]), "+f"(d[3])
        : "r"(a[0]), "r"(a[1]), "r"(a[2]), "r"(a[3]), "r"(b[0]), "r"(b[1]));
}
__device__ __forceinline__ void cpa16(u32 dst, const void* src) {
    asm volatile("cp.async.cg.shared.global [%0], [%1], 16;" :: "r"(dst), "l"(src));
}
#define CP_COMMIT()   asm volatile("cp.async.commit_group;")
#define CP_WAIT1()    asm volatile("cp.async.wait_group 1;")
#define CP_WAITALL()  asm volatile("cp.async.wait_group 0;")

// ============================================================================
// Weight transposes (rna-tf32 outputs)
// ============================================================================
__global__ void k_wtrans(const float* __restrict__ Wmax, const float* __restrict__ Wphi) {
    __shared__ float t[32][33];
    int z = blockIdx.z;
    const float* src = ((z & 1) ? Wphi : Wmax) + (size_t)(z >> 1) * 65536;
    float* dst = g_wT + (size_t)z * 65536;
    int e0 = blockIdx.x * 32, k0 = blockIdx.y * 32;
    int tx = threadIdx.x & 31, ty = threadIdx.x >> 5;
#pragma unroll
    for (int i = 0; i < 4; i++) t[ty + i * 8][tx] = src[(size_t)(k0 + ty + i * 8) * 256 + e0 + tx];
    __syncthreads();
#pragma unroll
    for (int i = 0; i < 4; i++)
        dst[(size_t)(e0 + ty + i * 8) * 256 + k0 + tx] = tfbits(t[tx][ty + i * 8]);
}
__global__ void k_wctrans(const float* __restrict__ Wc) {
    __shared__ float t[32][33];
    int k0 = blockIdx.x * 32, e0 = blockIdx.y * 32;
    int tx = threadIdx.x & 31, ty = threadIdx.x >> 5;
#pragma unroll
    for (int i = 0; i < 4; i++) t[ty + i * 8][tx] = Wc[(size_t)(k0 + ty + i * 8) * 256 + e0 + tx];
    __syncthreads();
#pragma unroll
    for (int i = 0; i < 4; i++)
        g_wcT[(size_t)(e0 + ty + i * 8) * 768 + k0 + tx] = tfbits(t[tx][ty + i * 8]);
}

// ============================================================================
// Kernel 1: gate softmax + z_sum (fp32 out). One warp per node.
// Wb rows padded to 10 floats (40B): 4 x LDS.64 per row; banks (10*lane)%32
// distinct within each 16-lane phase -> conflict-free.
// ============================================================================
__global__ void k_gate_zsum(const float* __restrict__ zs, const float* __restrict__ Wb,
                            const float* __restrict__ bb, int N) {
    extern __shared__ float swb[];  // 2048 * 10 floats = 80 KB
    int tid = threadIdx.x;
    for (int e = tid; e < 2048; e += blockDim.x) {
        const float2* src = (const float2*)(Wb + e * 8);
        float2* dst = (float2*)(swb + e * 10);
        dst[0] = src[0]; dst[1] = src[1]; dst[2] = src[2]; dst[3] = src[3];
    }
    __syncthreads();

    int lane = tid & 31, wid = tid >> 5;
    int wpb = blockDim.x >> 5, stride = wpb * gridDim.x;
    float bbv[8];
#pragma unroll
    for (int j = 0; j < 8; j++) bbv[j] = bb[j];

    for (int n = blockIdx.x * wpb + wid; n < N; n += stride) {
        float vals[MREL][8];
#pragma unroll
        for (int m = 0; m < MREL; m++) {
            const float* p = zs + ((size_t)m * N + n) * DDIM + lane;
#pragma unroll
            for (int i = 0; i < 8; i++) vals[m][i] = p[32 * i];
        }
        float lg[8] = {0.f,0.f,0.f,0.f,0.f,0.f,0.f,0.f};
#pragma unroll
        for (int m = 0; m < MREL; m++) {
#pragma unroll
            for (int i = 0; i < 8; i++) {
                const float2* w = (const float2*)(swb + (size_t)(m * DDIM + lane + 32 * i) * 10);
                float2 w0 = w[0], w1 = w[1], w2 = w[2], w3 = w[3];
                float v = vals[m][i];
                lg[0] = fmaf(v, w0.x, lg[0]); lg[1] = fmaf(v, w0.y, lg[1]);
                lg[2] = fmaf(v, w1.x, lg[2]); lg[3] = fmaf(v, w1.y, lg[3]);
                lg[4] = fmaf(v, w2.x, lg[4]); lg[5] = fmaf(v, w2.y, lg[5]);
                lg[6] = fmaf(v, w3.x, lg[6]); lg[7] = fmaf(v, w3.y, lg[7]);
            }
        }
#pragma unroll
        for (int off = 16; off > 0; off >>= 1) {
#pragma unroll
            for (int j = 0; j < 8; j++) lg[j] += __shfl_xor_sync(0xffffffffu, lg[j], off);
        }
        float mx = -1e30f;
#pragma unroll
        for (int j = 0; j < 8; j++) { lg[j] += bbv[j]; mx = fmaxf(mx, lg[j]); }
        float g[8], se = 0.f;
#pragma unroll
        for (int j = 0; j < 8; j++) { g[j] = expf(lg[j] - mx); se += g[j]; }
        float inv = 1.f / se;
        float* q = g_zsum + (size_t)n * DDIM + lane;
#pragma unroll
        for (int i = 0; i < 8; i++) {
            float a = 0.f;
#pragma unroll
            for (int m = 0; m < MREL; m++) a = fmaf(g[m], vals[m][i], a);
            q[32 * i] = a * inv;
        }
    }
}

// ============================================================================
// Kernel 2: fused dual-GEMM + fold. CTA tile 128 nodes x 64 e-cols, proj+phi
// per warp. K-chunk 64, 3-stage cp.async, prefetch distance 2, wait_group 1.
// ============================================================================
__global__ void __launch_bounds__(256, 1) k_maxphi_mma(
        const float* __restrict__ zs,
        const float* __restrict__ bmax, const float* __restrict__ bphi, int N) {
    extern __shared__ float sh[];
    u32 shb = (u32)__cvta_generic_to_shared(sh);
    float* sbm = sh;                    // [8][64]
    float* sbp = sh + 512;              // [8][64]
    float* sAf = sh + 1024;             // 3 x [128][68]
    float* sBf = sh + 1024 + 3 * 8704;  // 3 x [128][68]
    const u32 A0 = shb + 4096, B0 = shb + 4096 + 3 * 34816;

    int tid = threadIdx.x, wid = tid >> 5, lane = tid & 31;
    int g = lane >> 2, t4 = lane & 3;
    int warpM = wid & 3, warpN = wid >> 2;
    int e0 = blockIdx.x * 64, n0 = blockIdx.y * 128;

    for (int i = tid; i < MREL * 64; i += 256) {
        int m = i >> 6, c = i & 63;
        sbm[i] = bmax[m * DDIM + e0 + c];
        sbp[i] = bphi[m * DDIM + e0 + c];
    }

    auto stage = [&](int it) {
        int m = it >> 2, k0 = (it & 3) * 64, s = it % 3;
        const float* za = zs + (size_t)m * N * DDIM;
        const float* wb = g_wT + (size_t)m * 2 * 65536;
        u32 sa = A0 + s * 34816, sb = B0 + s * 34816;
#pragma unroll
        for (int j = 0; j < 8; j++) {
            int f = tid + j * 256;
            int row = f >> 4, kq = f & 15;
            int nr = n0 + row; if (nr >= N) nr = N - 1;
            cpa16(sa + row * 272 + kq * 16, za + (size_t)nr * DDIM + k0 + kq * 4);
        }
#pragma unroll
        for (int j = 0; j < 8; j++) {
            int f = tid + j * 256;
            int row = f >> 4, kq = f & 15;
            const float* src = wb + (row >= 64 ? 65536 : 0)
                               + (size_t)(e0 + (row & 63)) * 256 + k0 + kq * 4;
            cpa16(sb + row * 272 + kq * 16, src);
        }
    };

    stage(0); CP_COMMIT();
    stage(1); CP_COMMIT();

    float stP[32], stF1[32], stF2[32];
#pragma unroll
    for (int i = 0; i < 32; i++) { stP[i] = -3.0e38f; stF1[i] = 0.f; stF2[i] = 0.f; }

    float dP[2][4][4], dF[2][4][4];

    for (int it = 0; it < 32; it++) {
        int m = it >> 2, chunk = it & 3, s = it % 3;
        if (chunk == 0) {
#pragma unroll
            for (int mm = 0; mm < 2; mm++)
#pragma unroll
                for (int nn = 0; nn < 4; nn++)
#pragma unroll
                    for (int i = 0; i < 4; i++) { dP[mm][nn][i] = 0.f; dF[mm][nn][i] = 0.f; }
        }
        CP_WAIT1();
        __syncthreads();
        if (it + 2 < 32) { stage(it + 2); CP_COMMIT(); }

        const float* A  = sAf + s * 8704 + (warpM * 32 + g) * 68;
        const float* Bp = sBf + s * 8704 + (warpN * 32 + g) * 68;
        const float* Bf = Bp + 64 * 68;
#pragma unroll
        for (int ks = 0; ks < 8; ks++) {
            int kb = ks * 8 + t4;
            u32 a[2][4], bp[4][2], bf[4][2];
#pragma unroll
            for (int mm = 0; mm < 2; mm++) {
                const float* ar = A + mm * 16 * 68 + kb;
                a[mm][0] = f2tf(ar[0]);
                a[mm][1] = f2tf(ar[8 * 68]);
                a[mm][2] = f2tf(ar[4]);
                a[mm][3] = f2tf(ar[8 * 68 + 4]);
            }
#pragma unroll
            for (int nn = 0; nn < 4; nn++) {
                const float* bpr = Bp + nn * 8 * 68 + kb;
                bp[nn][0] = fasu(bpr[0]); bp[nn][1] = fasu(bpr[4]);
                const float* bfr = Bf + nn * 8 * 68 + kb;
                bf[nn][0] = fasu(bfr[0]); bf[nn][1] = fasu(bfr[4]);
            }
#pragma unroll
            for (int mm = 0; mm < 2; mm++)
#pragma unroll
                for (int nn = 0; nn < 4; nn++) {
                    mma8(dP[mm][nn], a[mm], bp[nn]);
                    mma8(dF[mm][nn], a[mm], bf[nn]);
                }
        }

        if (chunk == 3) {
#pragma unroll
            for (int nn = 0; nn < 4; nn++) {
                int cb = m * 64 + warpN * 32 + nn * 8 + t4 * 2;
                float bm0 = sbm[cb], bm1 = sbm[cb + 1];
                float bp0 = sbp[cb], bp1 = sbp[cb + 1];
#pragma unroll
                for (int mm = 0; mm < 2; mm++) {
                    int ix = mm * 16 + nn * 4;
                    stP[ix + 0] = fmaxf(stP[ix + 0], dP[mm][nn][0] + bm0);
                    stP[ix + 1] = fmaxf(stP[ix + 1], dP[mm][nn][1] + bm1);
                    stP[ix + 2] = fmaxf(stP[ix + 2], dP[mm][nn][2] + bm0);
                    stP[ix + 3] = fmaxf(stP[ix + 3], dP[mm][nn][3] + bm1);
                    float v0 = dF[mm][nn][0] + bp0, v1 = dF[mm][nn][1] + bp1;
                    float v2 = dF[mm][nn][2] + bp0, v3 = dF[mm][nn][3] + bp1;
                    stF1[ix + 0] += v0; stF2[ix + 0] = fmaf(v0, v0, stF2[ix + 0]);
                    stF1[ix + 1] += v1; stF2[ix + 1] = fmaf(v1, v1, stF2[ix + 1]);
                    stF1[ix + 2] += v2; stF2[ix + 2] = fmaf(v2, v2, stF2[ix + 2]);
                    stF1[ix + 3] += v3; stF2[ix + 3] = fmaf(v3, v3, stF2[ix + 3]);
                }
            }
        }
    }

#pragma unroll
    for (int mm = 0; mm < 2; mm++) {
#pragma unroll
        for (int h = 0; h < 2; h++) {
            int n = n0 + warpM * 32 + mm * 16 + g + h * 8;
            if (n >= N) continue;
#pragma unroll
            for (int nn = 0; nn < 4; nn++) {
                int ix = mm * 16 + nn * 4 + h * 2;
                int e = e0 + warpN * 32 + nn * 8 + t4 * 2;
                *(float2*)(g_zmax + (size_t)n * DDIM + e) = make_float2(stP[ix], stP[ix + 1]);
                float a0 = 0.5f * (stF1[ix] * stF1[ix] - stF2[ix]);
                float a1 = 0.5f * (stF1[ix + 1] * stF1[ix + 1] - stF2[ix + 1]);
                *(float2*)(g_zagr + (size_t)n * DDIM + e) = make_float2(a0, a1);
            }
        }
    }
}

// ============================================================================
// Kernel 3: combine GEMM over chunk range [c0, c1) of 12 (K = 64 per chunk),
// A-side hi/lo split (2 mmas). 2-stage cp.async (distance 1) so smem stays
// at 104 KB -> can co-reside with the gate kernel's 80 KB CTAs.
// finalize: add previous g_zpre partial + bias; else store raw partial.
// ============================================================================
__global__ void __launch_bounds__(256, 1) k_combine_mma(
        const float* __restrict__ bc, int N, int c0, int c1, int finalize) {
    extern __shared__ float sh[];
    u32 shb = (u32)__cvta_generic_to_shared(sh);
    float* sAf = sh;                 // 2 x [128][68]
    float* sBf = sh + 2 * 8704;      // 2 x [64][68]
    const u32 A0 = shb, B0 = shb + 2 * 34816;

    int tid = threadIdx.x, wid = tid >> 5, lane = tid & 31;
    int g = lane >> 2, t4 = lane & 3;
    int warpM = wid & 3, warpN = wid >> 2;
    int e0 = blockIdx.x * 64, n0 = blockIdx.y * 128;

    auto stage = [&](int c) {
        int k0 = c * 64, s = (c - c0) & 1;
        const float* src = (k0 < 256) ? g_zsum : (k0 < 512) ? g_zmax : g_zagr;
        int kc = k0 & 255;
        u32 sa = A0 + s * 34816, sb = B0 + s * 17408;
#pragma unroll
        for (int j = 0; j < 8; j++) {
            int f = tid + j * 256;
            int row = f >> 4, kq = f & 15;
            int nr = n0 + row; if (nr >= N) nr = N - 1;
            cpa16(sa + row * 272 + kq * 16, src + (size_t)nr * DDIM + kc + kq * 4);
        }
#pragma unroll
        for (int j = 0; j < 4; j++) {
            int f = tid + j * 256;
            int row = f >> 4, kq = f & 15;
            cpa16(sb + row * 272 + kq * 16, g_wcT + (size_t)(e0 + row) * 768 + k0 + kq * 4);
        }
    };

    stage(c0); CP_COMMIT();

    float d[2][4][4];
#pragma unroll
    for (int mm = 0; mm < 2; mm++)
#pragma unroll
        for (int nn = 0; nn < 4; nn++)
#pragma unroll
            for (int i = 0; i < 4; i++) d[mm][nn][i] = 0.f;

    for (int c = c0; c < c1; c++) {
        int s = (c - c0) & 1;
        CP_WAITALL();
        __syncthreads();
        if (c + 1 < c1) { stage(c + 1); CP_COMMIT(); }

        const float* A = sAf + s * 8704 + (warpM * 32 + g) * 68;
        const float* B = sBf + s * 4352 + (warpN * 32 + g) * 68;
#pragma unroll
        for (int ks = 0; ks < 8; ks++) {
            int kb = ks * 8 + t4;
            u32 ahi[2][4], alo[2][4], b[4][2];
#pragma unroll
            for (int mm = 0; mm < 2; mm++) {
                const float* ar = A + mm * 16 * 68 + kb;
                float r0 = ar[0], r1 = ar[8 * 68], r2 = ar[4], r3 = ar[8 * 68 + 4];
                ahi[mm][0] = f2tf(r0); alo[mm][0] = fasu(r0 - __uint_as_float(ahi[mm][0]));
                ahi[mm][1] = f2tf(r1); alo[mm][1] = fasu(r1 - __uint_as_float(ahi[mm][1]));
                ahi[mm][2] = f2tf(r2); alo[mm][2] = fasu(r2 - __uint_as_float(ahi[mm][2]));
                ahi[mm][3] = f2tf(r3); alo[mm][3] = fasu(r3 - __uint_as_float(ahi[mm][3]));
            }
#pragma unroll
            for (int nn = 0; nn < 4; nn++) {
                const float* br = B + nn * 8 * 68 + kb;
                b[nn][0] = fasu(br[0]); b[nn][1] = fasu(br[4]);
            }
#pragma unroll
            for (int mm = 0; mm < 2; mm++)
#pragma unroll
                for (int nn = 0; nn < 4; nn++) {
                    mma8(d[mm][nn], alo[mm], b[nn]);
                    mma8(d[mm][nn], ahi[mm], b[nn]);
                }
        }
    }

#pragma unroll
    for (int mm = 0; mm < 2; mm++) {
#pragma unroll
        for (int h = 0; h < 2; h++) {
            int n = n0 + warpM * 32 + mm * 16 + g + h * 8;
            if (n >= N) continue;
#pragma unroll
            for (int nn = 0; nn < 4; nn++) {
                int e = e0 + warpN * 32 + nn * 8 + t4 * 2;
                float* po = g_zpre + (size_t)n * DDIM + e;
                float v0 = d[mm][nn][h * 2], v1 = d[mm][nn][h * 2 + 1];
                if (finalize) {
                    float2 prev = *(float2*)po;
                    v0 += prev.x + __ldg(bc + e);
                    v1 += prev.y + __ldg(bc + e + 1);
                }
                *(float2*)po = make_float2(v0, v1);
            }
        }
    }
}

// ============================================================================
// Kernel 4: LayerNorm. One warp per node.
// ============================================================================
__global__ void k_ln(const float* __restrict__ gamma, const float* __restrict__ beta,
                     float* __restrict__ out, int N) {
    int tid = threadIdx.x;
    int lane = tid & 31, wid = tid >> 5;
    int n = blockIdx.x * (blockDim.x >> 5) + wid;
    if (n >= N) return;

    const float* p = g_zpre + (size_t)n * DDIM + lane * 8;
    float4 v0 = *(const float4*)p;
    float4 v1 = *(const float4*)(p + 4);
    float v[8] = {v0.x, v0.y, v0.z, v0.w, v1.x, v1.y, v1.z, v1.w};
    float s = 0.f, q = 0.f;
#pragma unroll
    for (int dd = 0; dd < 8; dd++) { s += v[dd]; q = fmaf(v[dd], v[dd], q); }
#pragma unroll
    for (int off = 16; off > 0; off >>= 1) {
        s += __shfl_xor_sync(0xffffffffu, s, off);
        q += __shfl_xor_sync(0xffffffffu, q, off);
    }
    float mean = s * (1.f / 256.f);
    float var = q * (1.f / 256.f) - mean * mean;
    float inv = rsqrtf(var + 1e-5f);

    const float* gp = gamma + lane * 8;
    const float* bp = beta + lane * 8;
    float4 g0 = *(const float4*)gp, g1 = *(const float4*)(gp + 4);
    float4 b0 = *(const float4*)bp, b1 = *(const float4*)(bp + 4);
    float gg[8] = {g0.x, g0.y, g0.z, g0.w, g1.x, g1.y, g1.z, g1.w};
    float bbv[8] = {b0.x, b0.y, b0.z, b0.w, b1.x, b1.y, b1.z, b1.w};
    float o[8];
#pragma unroll
    for (int dd = 0; dd < 8; dd++) o[dd] = fmaf((v[dd] - mean) * inv, gg[dd], bbv[dd]);

    float* qo = out + (size_t)n * DDIM + lane * 8;
    *(float4*)qo       = make_float4(o[0], o[1], o[2], o[3]);
    *(float4*)(qo + 4) = make_float4(o[4], o[5], o[6], o[7]);
}

// ============================================================================
extern "C" void kernel_launch(void* const* d_in, const int* in_sizes, int n_in,
                              void* d_out, int out_size) {
    const float* zs    = (const float*)d_in[0];
    const float* Wb    = (const float*)d_in[1];
    const float* bb    = (const float*)d_in[2];
    const float* Wmax  = (const float*)d_in[3];
    const float* bmax  = (const float*)d_in[4];
    const float* Wphi  = (const float*)d_in[5];
    const float* bphi  = (const float*)d_in[6];
    const float* Wc    = (const float*)d_in[7];
    const float* bc    = (const float*)d_in[8];
    const float* gamma = (const float*)d_in[9];
    const float* beta  = (const float*)d_in[10];
    float* out = (float*)d_out;

    int N = in_sizes[0] / (MREL * DDIM);
    int nt128 = (N + 127) / 128;

    static cudaStream_t s1 = 0;
    static cudaEvent_t evm = 0, ev1 = 0;
    static int configured = 0;
    if (!configured) {
        cudaFuncSetAttribute(k_gate_zsum, cudaFuncAttributeMaxDynamicSharedMemorySize, 81920);
        cudaFuncSetAttribute(k_maxphi_mma, cudaFuncAttributeMaxDynamicSharedMemorySize, 212992);
        cudaFuncSetAttribute(k_combine_mma, cudaFuncAttributeMaxDynamicSharedMemorySize, 104448);
        cudaStreamCreateWithFlags(&s1, cudaStreamNonBlocking);
        cudaEventCreateWithFlags(&evm, cudaEventDisableTiming);
        cudaEventCreateWithFlags(&ev1, cudaEventDisableTiming);
        configured = 1;
    }

    // s0 (capture-origin stream): transposes -> maxphi
    k_wtrans<<<dim3(8, 8, 16), 256>>>(Wmax, Wphi);
    k_wctrans<<<dim3(24, 8), 256>>>(Wc);
    k_maxphi_mma<<<dim3(4, nt128), 256, 212992>>>(zs, bmax, bphi, N);

    // fork: gate runs on s1, overlapped with combine_b on s0
    cudaEventRecord(evm, 0);
    cudaStreamWaitEvent(s1, evm, 0);
    k_gate_zsum<<<592, 256, 81920, s1>>>(zs, Wb, bb, N);
    cudaEventRecord(ev1, s1);

    // combine part B: k in [256, 768) -- depends only on maxphi outputs
    k_combine_mma<<<dim3(4, nt128), 256, 104448>>>(bc, N, 4, 12, 0);

    // join, then combine part A: k in [0, 256) (needs z_sum) + bias finalize
    cudaStreamWaitEvent(0, ev1, 0);
    k_combine_mma<<<dim3(4, nt128), 256, 104448>>>(bc, N, 0, 4, 1);

    k_ln<<<(N + 7) / 8, 256>>>(gamma, beta, out, N);
}

// round 10
// speedup vs baseline: 1.1795x; 1.1172x over previous
#include <cuda_runtime.h>
#include <math.h>

#define MREL 8
#define DDIM 256
#define MAXN 51200

typedef unsigned int u32;

// ---------------- scratch (no cudaMalloc allowed) ----------------
__device__ float g_zsum[(size_t)MAXN * DDIM];        // fp32 (unrounded)
__device__ float g_zmax[(size_t)MAXN * DDIM];        // fp32
__device__ float g_zagr[(size_t)MAXN * DDIM];        // fp32
__device__ float g_zpre[(size_t)MAXN * DDIM];        // fp32
__device__ float g_logits[(size_t)MAXN * MREL];      // fp32 gate logits
__device__ float g_wT[16 * 256 * 256];               // [m*2+mat][e][k] K-major, rna-tf32
__device__ float g_wcT[256 * 768];                   // [e][k] K-major, rna-tf32
__device__ float g_wbT[8 * 2048];                    // [j][k] K-major, rna-tf32

__device__ __forceinline__ u32 f2tf(float x) {       // round-to-nearest tf32
    u32 r; asm("cvt.rna.tf32.f32 %0, %1;" : "=r"(r) : "f"(x)); return r;
}
__device__ __forceinline__ float tfbits(float x) { return __uint_as_float(f2tf(x)); }
__device__ __forceinline__ u32 fasu(float x) { return __float_as_uint(x); }

__device__ __forceinline__ void mma8(float* d, const u32* a, const u32* b) {
    asm volatile(
        "mma.sync.aligned.m16n8k8.row.col.f32.tf32.tf32.f32 "
        "{%0,%1,%2,%3}, {%4,%5,%6,%7}, {%8,%9}, {%0,%1,%2,%3};"
        : "+f"(d[0]), "+f"(d[1]), "+f"(d[2]), "+f"(d[3])
        : "r"(a[0]), "r"(a[1]), "r"(a[2]), "r"(a[3]), "r"(b[0]), "r"(b[1]));
}
__device__ __forceinline__ void cpa16(u32 dst, const void* src) {
    asm volatile("cp.async.cg.shared.global [%0], [%1], 16;" :: "r"(dst), "l"(src));
}
#define CP_COMMIT()   asm volatile("cp.async.commit_group;")
#define CP_WAIT1()    asm volatile("cp.async.wait_group 1;")
#define CP_WAITALL()  asm volatile("cp.async.wait_group 0;")

// ============================================================================
// Weight transposes (rna-tf32 outputs)
// ============================================================================
__global__ void k_wtrans(const float* __restrict__ Wmax, const float* __restrict__ Wphi) {
    __shared__ float t[32][33];
    int z = blockIdx.z;
    const float* src = ((z & 1) ? Wphi : Wmax) + (size_t)(z >> 1) * 65536;
    float* dst = g_wT + (size_t)z * 65536;
    int e0 = blockIdx.x * 32, k0 = blockIdx.y * 32;
    int tx = threadIdx.x & 31, ty = threadIdx.x >> 5;
#pragma unroll
    for (int i = 0; i < 4; i++) t[ty + i * 8][tx] = src[(size_t)(k0 + ty + i * 8) * 256 + e0 + tx];
    __syncthreads();
#pragma unroll
    for (int i = 0; i < 4; i++)
        dst[(size_t)(e0 + ty + i * 8) * 256 + k0 + tx] = tfbits(t[tx][ty + i * 8]);
}
__global__ void k_wctrans(const float* __restrict__ Wc) {
    __shared__ float t[32][33];
    int k0 = blockIdx.x * 32, e0 = blockIdx.y * 32;
    int tx = threadIdx.x & 31, ty = threadIdx.x >> 5;
#pragma unroll
    for (int i = 0; i < 4; i++) t[ty + i * 8][tx] = Wc[(size_t)(k0 + ty + i * 8) * 256 + e0 + tx];
    __syncthreads();
#pragma unroll
    for (int i = 0; i < 4; i++)
        g_wcT[(size_t)(e0 + ty + i * 8) * 768 + k0 + tx] = tfbits(t[tx][ty + i * 8]);
}
// Wb [2048][8] -> g_wbT [8][2048], rna-tf32
__global__ void k_wbtrans(const float* __restrict__ Wb) {
    int k = blockIdx.x * 256 + threadIdx.x;   // 0..2047
    if (k < 2048) {
#pragma unroll
        for (int j = 0; j < 8; j++)
            g_wbT[j * 2048 + k] = tfbits(Wb[k * 8 + j]);
    }
}

// ============================================================================
// Kernel 1a: gate logits GEMM  logits[N,8] = cat[N,2048] @ Wb + bb.
// tf32 mma with A hi/lo split; B pre-rounded (g_wbT). CTA 128 nodes.
// 8 warps x m16 rows = 128 rows; n-dim = 8 (single col group, col = g).
// K = 2048 in chunks of 64, 2-stage cp.async.
// ============================================================================
__global__ void __launch_bounds__(256, 2) k_gate_logits(
        const float* __restrict__ zs, const float* __restrict__ bb, int N) {
    extern __shared__ float sh[];
    u32 shb = (u32)__cvta_generic_to_shared(sh);
    float* sAf = sh;                 // 2 x [128][68]
    float* sBf = sh + 2 * 8704;      // 2 x [8][68]
    const u32 A0 = shb, B0 = shb + 2 * 34816;

    int tid = threadIdx.x, wid = tid >> 5, lane = tid & 31;
    int g = lane >> 2, t4 = lane & 3;
    int n0 = blockIdx.x * 128;

    auto stage = [&](int c) {
        int m = c >> 2, kc = (c & 3) * 64, s = c & 1;
        const float* za = zs + (size_t)m * N * DDIM;
        u32 sa = A0 + s * 34816, sb = B0 + s * 2176;
#pragma unroll
        for (int j = 0; j < 8; j++) {
            int f = tid + j * 256;             // A: 2048 16B chunks
            int row = f >> 4, kq = f & 15;
            int nr = n0 + row; if (nr >= N) nr = N - 1;
            cpa16(sa + row * 272 + kq * 16, za + (size_t)nr * DDIM + kc + kq * 4);
        }
        if (tid < 128) {                       // B: 128 16B chunks (8 rows x 64k)
            int row = tid >> 4, kq = tid & 15;
            cpa16(sb + row * 272 + kq * 16, g_wbT + (size_t)row * 2048 + c * 64 + kq * 4);
        }
    };

    stage(0); CP_COMMIT();

    float d[4] = {0.f, 0.f, 0.f, 0.f};

    for (int c = 0; c < 32; c++) {
        int s = c & 1;
        CP_WAITALL();
        __syncthreads();
        if (c + 1 < 32) { stage(c + 1); CP_COMMIT(); }

        const float* A = sAf + s * 8704 + (wid * 16 + g) * 68;
        const float* B = sBf + s * 544 + g * 68;
#pragma unroll
        for (int ks = 0; ks < 8; ks++) {
            int kb = ks * 8 + t4;
            float r0 = A[kb], r1 = A[8 * 68 + kb], r2 = A[kb + 4], r3 = A[8 * 68 + kb + 4];
            u32 ahi[4], alo[4], b[2];
            ahi[0] = f2tf(r0); alo[0] = fasu(r0 - __uint_as_float(ahi[0]));
            ahi[1] = f2tf(r1); alo[1] = fasu(r1 - __uint_as_float(ahi[1]));
            ahi[2] = f2tf(r2); alo[2] = fasu(r2 - __uint_as_float(ahi[2]));
            ahi[3] = f2tf(r3); alo[3] = fasu(r3 - __uint_as_float(ahi[3]));
            b[0] = fasu(B[kb]); b[1] = fasu(B[kb + 4]);
            mma8(d, alo, b);
            mma8(d, ahi, b);
        }
    }

    float bb0 = __ldg(bb + t4 * 2), bb1 = __ldg(bb + t4 * 2 + 1);
#pragma unroll
    for (int h = 0; h < 2; h++) {
        int n = n0 + wid * 16 + g + h * 8;
        if (n < N)
            *(float2*)(g_logits + (size_t)n * 8 + t4 * 2) =
                make_float2(d[h * 2] + bb0, d[h * 2 + 1] + bb1);
    }
}

// ============================================================================
// Kernel 1b: streaming softmax + z_sum. One warp per node, zero smem,
// low regs -> co-resides with combine_mma CTAs in the fork.
// ============================================================================
__global__ void k_gate_zsum2(const float* __restrict__ zs, int N) {
    int tid = threadIdx.x;
    int lane = tid & 31, wid = tid >> 5;
    int n = blockIdx.x * 8 + wid;
    if (n >= N) return;

    const float* L = g_logits + (size_t)n * 8;
    float lg[8];
#pragma unroll
    for (int j = 0; j < 8; j++) lg[j] = __ldg(L + j);
    float mx = -1e30f;
#pragma unroll
    for (int j = 0; j < 8; j++) mx = fmaxf(mx, lg[j]);
    float gsm[8], se = 0.f;
#pragma unroll
    for (int j = 0; j < 8; j++) { gsm[j] = expf(lg[j] - mx); se += gsm[j]; }
    float inv = 1.f / se;
#pragma unroll
    for (int j = 0; j < 8; j++) gsm[j] *= inv;

    const float* base = zs + (size_t)n * DDIM + lane;
    float* q = g_zsum + (size_t)n * DDIM + lane;
    size_t mstr = (size_t)N * DDIM;
#pragma unroll
    for (int i = 0; i < 8; i++) {
        float v[8];
#pragma unroll
        for (int m = 0; m < 8; m++) v[m] = __ldg(base + m * mstr + 32 * i);
        float a = 0.f;
#pragma unroll
        for (int m = 0; m < 8; m++) a = fmaf(gsm[m], v[m], a);
        q[32 * i] = a;
    }
}

// ============================================================================
// Kernel 2: fused dual-GEMM + fold. CTA tile 128 nodes x 64 e-cols, proj+phi
// per warp. K-chunk 64, 3-stage cp.async, prefetch distance 2, wait_group 1.
// ============================================================================
__global__ void __launch_bounds__(256, 1) k_maxphi_mma(
        const float* __restrict__ zs,
        const float* __restrict__ bmax, const float* __restrict__ bphi, int N) {
    extern __shared__ float sh[];
    u32 shb = (u32)__cvta_generic_to_shared(sh);
    float* sbm = sh;                    // [8][64]
    float* sbp = sh + 512;              // [8][64]
    float* sAf = sh + 1024;             // 3 x [128][68]
    float* sBf = sh + 1024 + 3 * 8704;  // 3 x [128][68]
    const u32 A0 = shb + 4096, B0 = shb + 4096 + 3 * 34816;

    int tid = threadIdx.x, wid = tid >> 5, lane = tid & 31;
    int g = lane >> 2, t4 = lane & 3;
    int warpM = wid & 3, warpN = wid >> 2;
    int e0 = blockIdx.x * 64, n0 = blockIdx.y * 128;

    for (int i = tid; i < MREL * 64; i += 256) {
        int m = i >> 6, c = i & 63;
        sbm[i] = bmax[m * DDIM + e0 + c];
        sbp[i] = bphi[m * DDIM + e0 + c];
    }

    auto stage = [&](int it) {
        int m = it >> 2, k0 = (it & 3) * 64, s = it % 3;
        const float* za = zs + (size_t)m * N * DDIM;
        const float* wb = g_wT + (size_t)m * 2 * 65536;
        u32 sa = A0 + s * 34816, sb = B0 + s * 34816;
#pragma unroll
        for (int j = 0; j < 8; j++) {
            int f = tid + j * 256;
            int row = f >> 4, kq = f & 15;
            int nr = n0 + row; if (nr >= N) nr = N - 1;
            cpa16(sa + row * 272 + kq * 16, za + (size_t)nr * DDIM + k0 + kq * 4);
        }
#pragma unroll
        for (int j = 0; j < 8; j++) {
            int f = tid + j * 256;
            int row = f >> 4, kq = f & 15;
            const float* src = wb + (row >= 64 ? 65536 : 0)
                               + (size_t)(e0 + (row & 63)) * 256 + k0 + kq * 4;
            cpa16(sb + row * 272 + kq * 16, src);
        }
    };

    stage(0); CP_COMMIT();
    stage(1); CP_COMMIT();

    float stP[32], stF1[32], stF2[32];
#pragma unroll
    for (int i = 0; i < 32; i++) { stP[i] = -3.0e38f; stF1[i] = 0.f; stF2[i] = 0.f; }

    float dP[2][4][4], dF[2][4][4];

    for (int it = 0; it < 32; it++) {
        int m = it >> 2, chunk = it & 3, s = it % 3;
        if (chunk == 0) {
#pragma unroll
            for (int mm = 0; mm < 2; mm++)
#pragma unroll
                for (int nn = 0; nn < 4; nn++)
#pragma unroll
                    for (int i = 0; i < 4; i++) { dP[mm][nn][i] = 0.f; dF[mm][nn][i] = 0.f; }
        }
        CP_WAIT1();
        __syncthreads();
        if (it + 2 < 32) { stage(it + 2); CP_COMMIT(); }

        const float* A  = sAf + s * 8704 + (warpM * 32 + g) * 68;
        const float* Bp = sBf + s * 8704 + (warpN * 32 + g) * 68;
        const float* Bf = Bp + 64 * 68;
#pragma unroll
        for (int ks = 0; ks < 8; ks++) {
            int kb = ks * 8 + t4;
            u32 a[2][4], bp[4][2], bf[4][2];
#pragma unroll
            for (int mm = 0; mm < 2; mm++) {
                const float* ar = A + mm * 16 * 68 + kb;
                a[mm][0] = f2tf(ar[0]);
                a[mm][1] = f2tf(ar[8 * 68]);
                a[mm][2] = f2tf(ar[4]);
                a[mm][3] = f2tf(ar[8 * 68 + 4]);
            }
#pragma unroll
            for (int nn = 0; nn < 4; nn++) {
                const float* bpr = Bp + nn * 8 * 68 + kb;
                bp[nn][0] = fasu(bpr[0]); bp[nn][1] = fasu(bpr[4]);
                const float* bfr = Bf + nn * 8 * 68 + kb;
                bf[nn][0] = fasu(bfr[0]); bf[nn][1] = fasu(bfr[4]);
            }
#pragma unroll
            for (int mm = 0; mm < 2; mm++)
#pragma unroll
                for (int nn = 0; nn < 4; nn++) {
                    mma8(dP[mm][nn], a[mm], bp[nn]);
                    mma8(dF[mm][nn], a[mm], bf[nn]);
                }
        }

        if (chunk == 3) {
#pragma unroll
            for (int nn = 0; nn < 4; nn++) {
                int cb = m * 64 + warpN * 32 + nn * 8 + t4 * 2;
                float bm0 = sbm[cb], bm1 = sbm[cb + 1];
                float bp0 = sbp[cb], bp1 = sbp[cb + 1];
#pragma unroll
                for (int mm = 0; mm < 2; mm++) {
                    int ix = mm * 16 + nn * 4;
                    stP[ix + 0] = fmaxf(stP[ix + 0], dP[mm][nn][0] + bm0);
                    stP[ix + 1] = fmaxf(stP[ix + 1], dP[mm][nn][1] + bm1);
                    stP[ix + 2] = fmaxf(stP[ix + 2], dP[mm][nn][2] + bm0);
                    stP[ix + 3] = fmaxf(stP[ix + 3], dP[mm][nn][3] + bm1);
                    float v0 = dF[mm][nn][0] + bp0, v1 = dF[mm][nn][1] + bp1;
                    float v2 = dF[mm][nn][2] + bp0, v3 = dF[mm][nn][3] + bp1;
                    stF1[ix + 0] += v0; stF2[ix + 0] = fmaf(v0, v0, stF2[ix + 0]);
                    stF1[ix + 1] += v1; stF2[ix + 1] = fmaf(v1, v1, stF2[ix + 1]);
                    stF1[ix + 2] += v2; stF2[ix + 2] = fmaf(v2, v2, stF2[ix + 2]);
                    stF1[ix + 3] += v3; stF2[ix + 3] = fmaf(v3, v3, stF2[ix + 3]);
                }
            }
        }
    }

#pragma unroll
    for (int mm = 0; mm < 2; mm++) {
#pragma unroll
        for (int h = 0; h < 2; h++) {
            int n = n0 + warpM * 32 + mm * 16 + g + h * 8;
            if (n >= N) continue;
#pragma unroll
            for (int nn = 0; nn < 4; nn++) {
                int ix = mm * 16 + nn * 4 + h * 2;
                int e = e0 + warpN * 32 + nn * 8 + t4 * 2;
                *(float2*)(g_zmax + (size_t)n * DDIM + e) = make_float2(stP[ix], stP[ix + 1]);
                float a0 = 0.5f * (stF1[ix] * stF1[ix] - stF2[ix]);
                float a1 = 0.5f * (stF1[ix + 1] * stF1[ix + 1] - stF2[ix + 1]);
                *(float2*)(g_zagr + (size_t)n * DDIM + e) = make_float2(a0, a1);
            }
        }
    }
}

// ============================================================================
// Kernel 3: combine GEMM over chunk range [c0, c1) of 12 (K = 64 per chunk),
// A-side hi/lo split (2 mmas). 2-stage cp.async, 104 KB smem.
// finalize: add previous g_zpre partial + bias; else store raw partial.
// ============================================================================
__global__ void __launch_bounds__(256, 1) k_combine_mma(
        const float* __restrict__ bc, int N, int c0, int c1, int finalize) {
    extern __shared__ float sh[];
    u32 shb = (u32)__cvta_generic_to_shared(sh);
    float* sAf = sh;                 // 2 x [128][68]
    float* sBf = sh + 2 * 8704;      // 2 x [64][68]
    const u32 A0 = shb, B0 = shb + 2 * 34816;

    int tid = threadIdx.x, wid = tid >> 5, lane = tid & 31;
    int g = lane >> 2, t4 = lane & 3;
    int warpM = wid & 3, warpN = wid >> 2;
    int e0 = blockIdx.x * 64, n0 = blockIdx.y * 128;

    auto stage = [&](int c) {
        int k0 = c * 64, s = (c - c0) & 1;
        const float* src = (k0 < 256) ? g_zsum : (k0 < 512) ? g_zmax : g_zagr;
        int kc = k0 & 255;
        u32 sa = A0 + s * 34816, sb = B0 + s * 17408;
#pragma unroll
        for (int j = 0; j < 8; j++) {
            int f = tid + j * 256;
            int row = f >> 4, kq = f & 15;
            int nr = n0 + row; if (nr >= N) nr = N - 1;
            cpa16(sa + row * 272 + kq * 16, src + (size_t)nr * DDIM + kc + kq * 4);
        }
#pragma unroll
        for (int j = 0; j < 4; j++) {
            int f = tid + j * 256;
            int row = f >> 4, kq = f & 15;
            cpa16(sb + row * 272 + kq * 16, g_wcT + (size_t)(e0 + row) * 768 + k0 + kq * 4);
        }
    };

    stage(c0); CP_COMMIT();

    float d[2][4][4];
#pragma unroll
    for (int mm = 0; mm < 2; mm++)
#pragma unroll
        for (int nn = 0; nn < 4; nn++)
#pragma unroll
            for (int i = 0; i < 4; i++) d[mm][nn][i] = 0.f;

    for (int c = c0; c < c1; c++) {
        int s = (c - c0) & 1;
        CP_WAITALL();
        __syncthreads();
        if (c + 1 < c1) { stage(c + 1); CP_COMMIT(); }

        const float* A = sAf + s * 8704 + (warpM * 32 + g) * 68;
        const float* B = sBf + s * 4352 + (warpN * 32 + g) * 68;
#pragma unroll
        for (int ks = 0; ks < 8; ks++) {
            int kb = ks * 8 + t4;
            u32 ahi[2][4], alo[2][4], b[4][2];
#pragma unroll
            for (int mm = 0; mm < 2; mm++) {
                const float* ar = A + mm * 16 * 68 + kb;
                float r0 = ar[0], r1 = ar[8 * 68], r2 = ar[4], r3 = ar[8 * 68 + 4];
                ahi[mm][0] = f2tf(r0); alo[mm][0] = fasu(r0 - __uint_as_float(ahi[mm][0]));
                ahi[mm][1] = f2tf(r1); alo[mm][1] = fasu(r1 - __uint_as_float(ahi[mm][1]));
                ahi[mm][2] = f2tf(r2); alo[mm][2] = fasu(r2 - __uint_as_float(ahi[mm][2]));
                ahi[mm][3] = f2tf(r3); alo[mm][3] = fasu(r3 - __uint_as_float(ahi[mm][3]));
            }
#pragma unroll
            for (int nn = 0; nn < 4; nn++) {
                const float* br = B + nn * 8 * 68 + kb;
                b[nn][0] = fasu(br[0]); b[nn][1] = fasu(br[4]);
            }
#pragma unroll
            for (int mm = 0; mm < 2; mm++)
#pragma unroll
                for (int nn = 0; nn < 4; nn++) {
                    mma8(d[mm][nn], alo[mm], b[nn]);
                    mma8(d[mm][nn], ahi[mm], b[nn]);
                }
        }
    }

#pragma unroll
    for (int mm = 0; mm < 2; mm++) {
#pragma unroll
        for (int h = 0; h < 2; h++) {
            int n = n0 + warpM * 32 + mm * 16 + g + h * 8;
            if (n >= N) continue;
#pragma unroll
            for (int nn = 0; nn < 4; nn++) {
                int e = e0 + warpN * 32 + nn * 8 + t4 * 2;
                float* po = g_zpre + (size_t)n * DDIM + e;
                float v0 = d[mm][nn][h * 2], v1 = d[mm][nn][h * 2 + 1];
                if (finalize) {
                    float2 prev = *(float2*)po;
                    v0 += prev.x + __ldg(bc + e);
                    v1 += prev.y + __ldg(bc + e + 1);
                }
                *(float2*)po = make_float2(v0, v1);
            }
        }
    }
}

// ============================================================================
// Kernel 4: LayerNorm. One warp per node.
// ============================================================================
__global__ void k_ln(const float* __restrict__ gamma, const float* __restrict__ beta,
                     float* __restrict__ out, int N) {
    int tid = threadIdx.x;
    int lane = tid & 31, wid = tid >> 5;
    int n = blockIdx.x * (blockDim.x >> 5) + wid;
    if (n >= N) return;

    const float* p = g_zpre + (size_t)n * DDIM + lane * 8;
    float4 v0 = *(const float4*)p;
    float4 v1 = *(const float4*)(p + 4);
    float v[8] = {v0.x, v0.y, v0.z, v0.w, v1.x, v1.y, v1.z, v1.w};
    float s = 0.f, q = 0.f;
#pragma unroll
    for (int dd = 0; dd < 8; dd++) { s += v[dd]; q = fmaf(v[dd], v[dd], q); }
#pragma unroll
    for (int off = 16; off > 0; off >>= 1) {
        s += __shfl_xor_sync(0xffffffffu, s, off);
        q += __shfl_xor_sync(0xffffffffu, q, off);
    }
    float mean = s * (1.f / 256.f);
    float var = q * (1.f / 256.f) - mean * mean;
    float inv = rsqrtf(var + 1e-5f);

    const float* gp = gamma + lane * 8;
    const float* bp = beta + lane * 8;
    float4 g0 = *(const float4*)gp, g1 = *(const float4*)(gp + 4);
    float4 b0 = *(const float4*)bp, b1 = *(const float4*)(bp + 4);
    float gg[8] = {g0.x, g0.y, g0.z, g0.w, g1.x, g1.y, g1.z, g1.w};
    float bbv[8] = {b0.x, b0.y, b0.z, b0.w, b1.x, b1.y, b1.z, b1.w};
    float o[8];
#pragma unroll
    for (int dd = 0; dd < 8; dd++) o[dd] = fmaf((v[dd] - mean) * inv, gg[dd], bbv[dd]);

    float* qo = out + (size_t)n * DDIM + lane * 8;
    *(float4*)qo       = make_float4(o[0], o[1], o[2], o[3]);
    *(float4*)(qo + 4) = make_float4(o[4], o[5], o[6], o[7]);
}

// ============================================================================
extern "C" void kernel_launch(void* const* d_in, const int* in_sizes, int n_in,
                              void* d_out, int out_size) {
    const float* zs    = (const float*)d_in[0];
    const float* Wb    = (const float*)d_in[1];
    const float* bb    = (const float*)d_in[2];
    const float* Wmax  = (const float*)d_in[3];
    const float* bmax  = (const float*)d_in[4];
    const float* Wphi  = (const float*)d_in[5];
    const float* bphi  = (const float*)d_in[6];
    const float* Wc    = (const float*)d_in[7];
    const float* bc    = (const float*)d_in[8];
    const float* gamma = (const float*)d_in[9];
    const float* beta  = (const float*)d_in[10];
    float* out = (float*)d_out;

    int N = in_sizes[0] / (MREL * DDIM);
    int nt128 = (N + 127) / 128;

    static cudaStream_t s1 = 0;
    static cudaEvent_t evm = 0, ev1 = 0;
    static int configured = 0;
    if (!configured) {
        cudaFuncSetAttribute(k_gate_logits, cudaFuncAttributeMaxDynamicSharedMemorySize, 73984);
        cudaFuncSetAttribute(k_maxphi_mma, cudaFuncAttributeMaxDynamicSharedMemorySize, 212992);
        cudaFuncSetAttribute(k_combine_mma, cudaFuncAttributeMaxDynamicSharedMemorySize, 104448);
        cudaStreamCreateWithFlags(&s1, cudaStreamNonBlocking);
        cudaEventCreateWithFlags(&evm, cudaEventDisableTiming);
        cudaEventCreateWithFlags(&ev1, cudaEventDisableTiming);
        configured = 1;
    }

    // s1: Wb transpose (independent of everything on s0)
    k_wbtrans<<<8, 256, 0, s1>>>(Wb);

    // s0: weight transposes -> maxphi
    k_wtrans<<<dim3(8, 8, 16), 256>>>(Wmax, Wphi);
    k_wctrans<<<dim3(24, 8), 256>>>(Wc);
    k_maxphi_mma<<<dim3(4, nt128), 256, 212992>>>(zs, bmax, bphi, N);

    // fork: gate pipeline on s1 overlapped with combine_b on s0
    cudaEventRecord(evm, 0);
    cudaStreamWaitEvent(s1, evm, 0);
    k_gate_logits<<<nt128, 256, 73984, s1>>>(zs, bb, N);
    k_gate_zsum2<<<(N + 7) / 8, 256, 0, s1>>>(zs, N);
    cudaEventRecord(ev1, s1);

    // combine part B: k in [256, 768) -- depends only on maxphi outputs
    k_combine_mma<<<dim3(4, nt128), 256, 104448>>>(bc, N, 4, 12, 0);

    // join, then combine part A: k in [0, 256) (needs z_sum) + bias finalize
    cudaStreamWaitEvent(0, ev1, 0);
    k_combine_mma<<<dim3(4, nt128), 256, 104448>>>(bc, N, 0, 4, 1);

    k_ln<<<(N + 7) / 8, 256>>>(gamma, beta, out, N);
}

// round 12
// speedup vs baseline: 1.6146x; 1.3689x over previous
#include <cuda_runtime.h>
#include <cuda_fp16.h>
#include <math.h>

#define MREL 8
#define DDIM 256
#define MAXN 51200

typedef unsigned int u32;

// ---------------- scratch (no cudaMalloc allowed) ----------------
__device__ __half g_zsh[(size_t)MREL * MAXN * DDIM]; // fp16 copy of zs
__device__ float g_zsum[(size_t)MAXN * DDIM];        // fp32
__device__ float g_zmax[(size_t)MAXN * DDIM];        // fp32
__device__ float g_zagr[(size_t)MAXN * DDIM];        // fp32
__device__ float g_zpre[(size_t)MAXN * DDIM];        // fp32
__device__ float g_logits[(size_t)MAXN * MREL];      // fp32
__device__ __half g_wTh[16 * 256 * 256];             // [m*2+mat][e][k] K-major fp16
__device__ __half g_wcTh[256 * 768];                 // [e][k] K-major fp16
__device__ __half g_wbTh[8 * 2048];                  // [j][k] K-major fp16

__device__ __forceinline__ u32 h2u(__half2 h) { return *(u32*)&h; }

// m16n8k16 fp16 mma, fp32 accum
__device__ __forceinline__ void mma16h(float* d, const u32* a, const u32* b) {
    asm volatile(
        "mma.sync.aligned.m16n8k16.row.col.f32.f16.f16.f32 "
        "{%0,%1,%2,%3}, {%4,%5,%6,%7}, {%8,%9}, {%0,%1,%2,%3};"
        : "+f"(d[0]), "+f"(d[1]), "+f"(d[2]), "+f"(d[3])
        : "r"(a[0]), "r"(a[1]), "r"(a[2]), "r"(a[3]), "r"(b[0]), "r"(b[1]));
}
__device__ __forceinline__ void cpa16(u32 dst, const void* src) {
    asm volatile("cp.async.cg.shared.global [%0], [%1], 16;" :: "r"(dst), "l"(src));
}
#define CP_COMMIT()   asm volatile("cp.async.commit_group;")
#define CP_WAIT1()    asm volatile("cp.async.wait_group 1;")
#define CP_WAITALL()  asm volatile("cp.async.wait_group 0;")

// hi/lo fp16 split of a float pair -> two packed b32
__device__ __forceinline__ void split2(float x, float y, u32& hi, u32& lo) {
    __half2 h = __floats2half2_rn(x, y);
    hi = h2u(h);
    __half2 l = __floats2half2_rn(x - __low2float(h), y - __high2float(h));
    lo = h2u(l);
}

// ============================================================================
// zs fp32 -> fp16 copy
// ============================================================================
__global__ void k_cvt_zs(const float* __restrict__ zs, long long n4) {
    long long i = blockIdx.x * (long long)blockDim.x + threadIdx.x;
    long long stride = (long long)gridDim.x * blockDim.x;
    for (; i < n4; i += stride) {
        float4 v = ((const float4*)zs)[i];
        __half2 h0 = __floats2half2_rn(v.x, v.y);
        __half2 h1 = __floats2half2_rn(v.z, v.w);
        ((uint2*)g_zsh)[i] = make_uint2(h2u(h0), h2u(h1));
    }
}

// ============================================================================
// Weight transposes (fp16 outputs, K-major)
// ============================================================================
__global__ void k_wtrans(const float* __restrict__ Wmax, const float* __restrict__ Wphi) {
    __shared__ float t[32][33];
    int z = blockIdx.z;
    const float* src = ((z & 1) ? Wphi : Wmax) + (size_t)(z >> 1) * 65536;
    __half* dst = g_wTh + (size_t)z * 65536;
    int e0 = blockIdx.x * 32, k0 = blockIdx.y * 32;
    int tx = threadIdx.x & 31, ty = threadIdx.x >> 5;
#pragma unroll
    for (int i = 0; i < 4; i++) t[ty + i * 8][tx] = src[(size_t)(k0 + ty + i * 8) * 256 + e0 + tx];
    __syncthreads();
#pragma unroll
    for (int i = 0; i < 4; i++)
        dst[(size_t)(e0 + ty + i * 8) * 256 + k0 + tx] = __float2half_rn(t[tx][ty + i * 8]);
}
__global__ void k_wctrans(const float* __restrict__ Wc) {
    __shared__ float t[32][33];
    int k0 = blockIdx.x * 32, e0 = blockIdx.y * 32;
    int tx = threadIdx.x & 31, ty = threadIdx.x >> 5;
#pragma unroll
    for (int i = 0; i < 4; i++) t[ty + i * 8][tx] = Wc[(size_t)(k0 + ty + i * 8) * 256 + e0 + tx];
    __syncthreads();
#pragma unroll
    for (int i = 0; i < 4; i++)
        g_wcTh[(size_t)(e0 + ty + i * 8) * 768 + k0 + tx] = __float2half_rn(t[tx][ty + i * 8]);
}
__global__ void k_wbtrans(const float* __restrict__ Wb) {
    int k = blockIdx.x * 256 + threadIdx.x;
    if (k < 2048) {
#pragma unroll
        for (int j = 0; j < 8; j++)
            g_wbTh[j * 2048 + k] = __float2half_rn(Wb[k * 8 + j]);
    }
}

// ============================================================================
// Kernel 1a: gate logits GEMM (fp16 mma, A hi/lo split in-register).
// CTA 128 nodes; 8 warps x 16 rows; n = 8. K = 2048 in 64-chunks, 2-stage.
// smem: A fp32 2 x 34816 | B fp16 2 x 1152 = 71936 B.
// ============================================================================
__global__ void __launch_bounds__(256, 2) k_gate_logits(
        const float* __restrict__ zs, const float* __restrict__ bb, int N) {
    extern __shared__ float sh[];
    u32 shb = (u32)__cvta_generic_to_shared(sh);
    float* sAf = sh;                                  // 2 x [128][68] fp32
    const u32 A0 = shb, B0 = shb + 2 * 34816;
    const u32* Bw = (const u32*)((const char*)sh + 2 * 34816);

    int tid = threadIdx.x, wid = tid >> 5, lane = tid & 31;
    int g = lane >> 2, t4 = lane & 3;
    int n0 = blockIdx.x * 128;

    auto stage = [&](int c) {
        int m = c >> 2, kc = (c & 3) * 64, s = c & 1;
        const float* za = zs + (size_t)m * N * DDIM;
        u32 sa = A0 + s * 34816, sb = B0 + s * 1152;
#pragma unroll
        for (int j = 0; j < 8; j++) {
            int f = tid + j * 256;
            int row = f >> 4, kq = f & 15;
            int nr = n0 + row; if (nr >= N) nr = N - 1;
            cpa16(sa + row * 272 + kq * 16, za + (size_t)nr * DDIM + kc + kq * 4);
        }
        if (tid < 64) {                                // B: 8 rows x 128B
            int row = tid >> 3, kq = tid & 7;
            cpa16(sb + row * 144 + kq * 16, g_wbTh + (size_t)row * 2048 + c * 64 + kq * 8);
        }
    };

    stage(0); CP_COMMIT();

    float d[4] = {0.f, 0.f, 0.f, 0.f};

    for (int c = 0; c < 32; c++) {
        int s = c & 1;
        CP_WAITALL();
        __syncthreads();
        if (c + 1 < 32) { stage(c + 1); CP_COMMIT(); }

        const float* A = sAf + s * 8704 + (wid * 16 + g) * 68;
        const u32* B = Bw + s * 288 + g * 36;
#pragma unroll
        for (int ks = 0; ks < 4; ks++) {
            int kf = ks * 16 + 2 * t4;
            float2 p0 = *(const float2*)(A + kf);
            float2 p1 = *(const float2*)(A + 8 * 68 + kf);
            float2 p2 = *(const float2*)(A + kf + 8);
            float2 p3 = *(const float2*)(A + 8 * 68 + kf + 8);
            u32 ahi[4], alo[4], b[2];
            split2(p0.x, p0.y, ahi[0], alo[0]);
            split2(p1.x, p1.y, ahi[1], alo[1]);
            split2(p2.x, p2.y, ahi[2], alo[2]);
            split2(p3.x, p3.y, ahi[3], alo[3]);
            b[0] = B[ks * 8 + t4];
            b[1] = B[ks * 8 + t4 + 4];
            mma16h(d, alo, b);
            mma16h(d, ahi, b);
        }
    }

    float bb0 = __ldg(bb + t4 * 2), bb1 = __ldg(bb + t4 * 2 + 1);
#pragma unroll
    for (int h = 0; h < 2; h++) {
        int n = n0 + wid * 16 + g + h * 8;
        if (n < N)
            *(float2*)(g_logits + (size_t)n * 8 + t4 * 2) =
                make_float2(d[h * 2] + bb0, d[h * 2 + 1] + bb1);
    }
}

// ============================================================================
// Kernel 1b: streaming softmax + z_sum (fp32 zs, exact). One warp per node.
// ============================================================================
__global__ void k_gate_zsum2(const float* __restrict__ zs, int N) {
    int tid = threadIdx.x;
    int lane = tid & 31, wid = tid >> 5;
    int n = blockIdx.x * 8 + wid;
    if (n >= N) return;

    const float* L = g_logits + (size_t)n * 8;
    float lg[8];
#pragma unroll
    for (int j = 0; j < 8; j++) lg[j] = __ldg(L + j);
    float mx = -1e30f;
#pragma unroll
    for (int j = 0; j < 8; j++) mx = fmaxf(mx, lg[j]);
    float gsm[8], se = 0.f;
#pragma unroll
    for (int j = 0; j < 8; j++) { gsm[j] = expf(lg[j] - mx); se += gsm[j]; }
    float inv = 1.f / se;
#pragma unroll
    for (int j = 0; j < 8; j++) gsm[j] *= inv;

    const float* base = zs + (size_t)n * DDIM + lane;
    float* q = g_zsum + (size_t)n * DDIM + lane;
    size_t mstr = (size_t)N * DDIM;
#pragma unroll
    for (int i = 0; i < 8; i++) {
        float v[8];
#pragma unroll
        for (int m = 0; m < 8; m++) v[m] = __ldg(base + m * mstr + 32 * i);
        float a = 0.f;
#pragma unroll
        for (int m = 0; m < 8; m++) a = fmaf(gsm[m], v[m], a);
        q[32 * i] = a;
    }
}

// ============================================================================
// Kernel 2: fused dual-GEMM + fold, fp16 m16n8k16. CTA 128 nodes x 64 e-cols,
// proj+phi per warp. K-chunk 64, 3-stage cp.async, distance 2.
// smem: biases 4096 | A fp16 3 x 18432 | B fp16 3 x 18432 = 114688 B.
// ============================================================================
__global__ void __launch_bounds__(256, 1) k_maxphi_mma(
        const float* __restrict__ bmax, const float* __restrict__ bphi, int N) {
    extern __shared__ float sh[];
    u32 shb = (u32)__cvta_generic_to_shared(sh);
    float* sbm = sh;                    // [8][64]
    float* sbp = sh + 512;              // [8][64]
    const u32 A0 = shb + 4096, B0 = shb + 4096 + 3 * 18432;
    const u32* Aw = (const u32*)((const char*)sh + 4096);
    const u32* Bw = (const u32*)((const char*)sh + 4096 + 3 * 18432);

    int tid = threadIdx.x, wid = tid >> 5, lane = tid & 31;
    int g = lane >> 2, t4 = lane & 3;
    int warpM = wid & 3, warpN = wid >> 2;
    int e0 = blockIdx.x * 64, n0 = blockIdx.y * 128;

    for (int i = tid; i < MREL * 64; i += 256) {
        int m = i >> 6, c = i & 63;
        sbm[i] = bmax[m * DDIM + e0 + c];
        sbp[i] = bphi[m * DDIM + e0 + c];
    }

    auto stage = [&](int it) {
        int m = it >> 2, k0 = (it & 3) * 64, s = it % 3;
        const __half* za = g_zsh + (size_t)m * N * DDIM;
        const __half* wb = g_wTh + (size_t)m * 2 * 65536;
        u32 sa = A0 + s * 18432, sb = B0 + s * 18432;
#pragma unroll
        for (int j = 0; j < 4; j++) {
            int f = tid + j * 256;             // A: 1024 chunks (128 rows x 8)
            int row = f >> 3, kq = f & 7;
            int nr = n0 + row; if (nr >= N) nr = N - 1;
            cpa16(sa + row * 144 + kq * 16, za + (size_t)nr * DDIM + k0 + kq * 8);
        }
#pragma unroll
        for (int j = 0; j < 4; j++) {
            int f = tid + j * 256;             // B: 1024 chunks
            int row = f >> 3, kq = f & 7;
            const __half* src = wb + (row >= 64 ? 65536 : 0)
                                + (size_t)(e0 + (row & 63)) * 256 + k0 + kq * 8;
            cpa16(sb + row * 144 + kq * 16, src);
        }
    };

    stage(0); CP_COMMIT();
    stage(1); CP_COMMIT();

    float stP[32], stF1[32], stF2[32];
#pragma unroll
    for (int i = 0; i < 32; i++) { stP[i] = -3.0e38f; stF1[i] = 0.f; stF2[i] = 0.f; }

    float dP[2][4][4], dF[2][4][4];

    for (int it = 0; it < 32; it++) {
        int m = it >> 2, chunk = it & 3, s = it % 3;
        if (chunk == 0) {
#pragma unroll
            for (int mm = 0; mm < 2; mm++)
#pragma unroll
                for (int nn = 0; nn < 4; nn++)
#pragma unroll
                    for (int i = 0; i < 4; i++) { dP[mm][nn][i] = 0.f; dF[mm][nn][i] = 0.f; }
        }
        CP_WAIT1();
        __syncthreads();
        if (it + 2 < 32) { stage(it + 2); CP_COMMIT(); }

        int abase = s * 4608 + (warpM * 32 + g) * 36;
        int bbase = s * 4608 + (warpN * 32 + g) * 36;
#pragma unroll
        for (int ks = 0; ks < 4; ks++) {
            int ko = ks * 8 + t4;
            u32 a[2][4], bp[4][2], bf[4][2];
#pragma unroll
            for (int mm = 0; mm < 2; mm++) {
                int ab = abase + mm * 16 * 36 + ko;
                a[mm][0] = Aw[ab];
                a[mm][1] = Aw[ab + 8 * 36];
                a[mm][2] = Aw[ab + 4];
                a[mm][3] = Aw[ab + 8 * 36 + 4];
            }
#pragma unroll
            for (int nn = 0; nn < 4; nn++) {
                int bb_ = bbase + nn * 8 * 36 + ko;
                bp[nn][0] = Bw[bb_];           bp[nn][1] = Bw[bb_ + 4];
                bf[nn][0] = Bw[bb_ + 64 * 36]; bf[nn][1] = Bw[bb_ + 64 * 36 + 4];
            }
#pragma unroll
            for (int mm = 0; mm < 2; mm++)
#pragma unroll
                for (int nn = 0; nn < 4; nn++) {
                    mma16h(dP[mm][nn], a[mm], bp[nn]);
                    mma16h(dF[mm][nn], a[mm], bf[nn]);
                }
        }

        if (chunk == 3) {
#pragma unroll
            for (int nn = 0; nn < 4; nn++) {
                int cb = m * 64 + warpN * 32 + nn * 8 + t4 * 2;
                float bm0 = sbm[cb], bm1 = sbm[cb + 1];
                float bp0 = sbp[cb], bp1 = sbp[cb + 1];
#pragma unroll
                for (int mm = 0; mm < 2; mm++) {
                    int ix = mm * 16 + nn * 4;
                    stP[ix + 0] = fmaxf(stP[ix + 0], dP[mm][nn][0] + bm0);
                    stP[ix + 1] = fmaxf(stP[ix + 1], dP[mm][nn][1] + bm1);
                    stP[ix + 2] = fmaxf(stP[ix + 2], dP[mm][nn][2] + bm0);
                    stP[ix + 3] = fmaxf(stP[ix + 3], dP[mm][nn][3] + bm1);
                    float v0 = dF[mm][nn][0] + bp0, v1 = dF[mm][nn][1] + bp1;
                    float v2 = dF[mm][nn][2] + bp0, v3 = dF[mm][nn][3] + bp1;
                    stF1[ix + 0] += v0; stF2[ix + 0] = fmaf(v0, v0, stF2[ix + 0]);
                    stF1[ix + 1] += v1; stF2[ix + 1] = fmaf(v1, v1, stF2[ix + 1]);
                    stF1[ix + 2] += v2; stF2[ix + 2] = fmaf(v2, v2, stF2[ix + 2]);
                    stF1[ix + 3] += v3; stF2[ix + 3] = fmaf(v3, v3, stF2[ix + 3]);
                }
            }
        }
    }

#pragma unroll
    for (int mm = 0; mm < 2; mm++) {
#pragma unroll
        for (int h = 0; h < 2; h++) {
            int n = n0 + warpM * 32 + mm * 16 + g + h * 8;
            if (n >= N) continue;
#pragma unroll
            for (int nn = 0; nn < 4; nn++) {
                int ix = mm * 16 + nn * 4 + h * 2;
                int e = e0 + warpN * 32 + nn * 8 + t4 * 2;
                *(float2*)(g_zmax + (size_t)n * DDIM + e) = make_float2(stP[ix], stP[ix + 1]);
                float a0 = 0.5f * (stF1[ix] * stF1[ix] - stF2[ix]);
                float a1 = 0.5f * (stF1[ix + 1] * stF1[ix + 1] - stF2[ix + 1]);
                *(float2*)(g_zagr + (size_t)n * DDIM + e) = make_float2(a0, a1);
            }
        }
    }
}

// ============================================================================
// Kernel 3: combine GEMM chunks [c0,c1) of 12 (K=64 each), fp16 mma with
// A-side hi/lo split in-register (A staged fp32). B = g_wcTh fp16.
// smem: A fp32 2 x 34816 | B fp16 2 x 9216 = 88064 B.
// ============================================================================
__global__ void __launch_bounds__(256, 1) k_combine_mma(
        const float* __restrict__ bc, int N, int c0, int c1, int finalize) {
    extern __shared__ float sh[];
    u32 shb = (u32)__cvta_generic_to_shared(sh);
    float* sAf = sh;                 // 2 x [128][68] fp32
    const u32 A0 = shb, B0 = shb + 2 * 34816;
    const u32* Bw = (const u32*)((const char*)sh + 2 * 34816);

    int tid = threadIdx.x, wid = tid >> 5, lane = tid & 31;
    int g = lane >> 2, t4 = lane & 3;
    int warpM = wid & 3, warpN = wid >> 2;
    int e0 = blockIdx.x * 64, n0 = blockIdx.y * 128;

    auto stage = [&](int c) {
        int k0 = c * 64, s = (c - c0) & 1;
        const float* src = (k0 < 256) ? g_zsum : (k0 < 512) ? g_zmax : g_zagr;
        int kc = k0 & 255;
        u32 sa = A0 + s * 34816, sb = B0 + s * 9216;
#pragma unroll
        for (int j = 0; j < 8; j++) {
            int f = tid + j * 256;
            int row = f >> 4, kq = f & 15;
            int nr = n0 + row; if (nr >= N) nr = N - 1;
            cpa16(sa + row * 272 + kq * 16, src + (size_t)nr * DDIM + kc + kq * 4);
        }
#pragma unroll
        for (int j = 0; j < 2; j++) {
            int f = tid + j * 256;             // B: 512 chunks (64 rows x 8)
            int row = f >> 3, kq = f & 7;
            cpa16(sb + row * 144 + kq * 16, g_wcTh + (size_t)(e0 + row) * 768 + k0 + kq * 8);
        }
    };

    stage(c0); CP_COMMIT();

    float d[2][4][4];
#pragma unroll
    for (int mm = 0; mm < 2; mm++)
#pragma unroll
        for (int nn = 0; nn < 4; nn++)
#pragma unroll
            for (int i = 0; i < 4; i++) d[mm][nn][i] = 0.f;

    for (int c = c0; c < c1; c++) {
        int s = (c - c0) & 1;
        CP_WAITALL();
        __syncthreads();
        if (c + 1 < c1) { stage(c + 1); CP_COMMIT(); }

        const float* A = sAf + s * 8704 + (warpM * 32 + g) * 68;
        const u32* B = Bw + s * 2304 + (warpN * 32 + g) * 36;
#pragma unroll
        for (int ks = 0; ks < 4; ks++) {
            int kf = ks * 16 + 2 * t4;
            u32 ahi[2][4], alo[2][4], b[4][2];
#pragma unroll
            for (int mm = 0; mm < 2; mm++) {
                const float* ar = A + mm * 16 * 68;
                float2 p0 = *(const float2*)(ar + kf);
                float2 p1 = *(const float2*)(ar + 8 * 68 + kf);
                float2 p2 = *(const float2*)(ar + kf + 8);
                float2 p3 = *(const float2*)(ar + 8 * 68 + kf + 8);
                split2(p0.x, p0.y, ahi[mm][0], alo[mm][0]);
                split2(p1.x, p1.y, ahi[mm][1], alo[mm][1]);
                split2(p2.x, p2.y, ahi[mm][2], alo[mm][2]);
                split2(p3.x, p3.y, ahi[mm][3], alo[mm][3]);
            }
#pragma unroll
            for (int nn = 0; nn < 4; nn++) {
                int bb_ = nn * 8 * 36 + ks * 8 + t4;
                b[nn][0] = B[bb_]; b[nn][1] = B[bb_ + 4];
            }
#pragma unroll
            for (int mm = 0; mm < 2; mm++)
#pragma unroll
                for (int nn = 0; nn < 4; nn++) {
                    mma16h(d[mm][nn], alo[mm], b[nn]);
                    mma16h(d[mm][nn], ahi[mm], b[nn]);
                }
        }
    }

#pragma unroll
    for (int mm = 0; mm < 2; mm++) {
#pragma unroll
        for (int h = 0; h < 2; h++) {
            int n = n0 + warpM * 32 + mm * 16 + g + h * 8;
            if (n >= N) continue;
#pragma unroll
            for (int nn = 0; nn < 4; nn++) {
                int e = e0 + warpN * 32 + nn * 8 + t4 * 2;
                float* po = g_zpre + (size_t)n * DDIM + e;
                float v0 = d[mm][nn][h * 2], v1 = d[mm][nn][h * 2 + 1];
                if (finalize) {
                    float2 prev = *(float2*)po;
                    v0 += prev.x + __ldg(bc + e);
                    v1 += prev.y + __ldg(bc + e + 1);
                }
                *(float2*)po = make_float2(v0, v1);
            }
        }
    }
}

// ============================================================================
// Kernel 4: LayerNorm. One warp per node.
// ============================================================================
__global__ void k_ln(const float* __restrict__ gamma, const float* __restrict__ beta,
                     float* __restrict__ out, int N) {
    int tid = threadIdx.x;
    int lane = tid & 31, wid = tid >> 5;
    int n = blockIdx.x * (blockDim.x >> 5) + wid;
    if (n >= N) return;

    const float* p = g_zpre + (size_t)n * DDIM + lane * 8;
    float4 v0 = *(const float4*)p;
    float4 v1 = *(const float4*)(p + 4);
    float v[8] = {v0.x, v0.y, v0.z, v0.w, v1.x, v1.y, v1.z, v1.w};
    float s = 0.f, q = 0.f;
#pragma unroll
    for (int dd = 0; dd < 8; dd++) { s += v[dd]; q = fmaf(v[dd], v[dd], q); }
#pragma unroll
    for (int off = 16; off > 0; off >>= 1) {
        s += __shfl_xor_sync(0xffffffffu, s, off);
        q += __shfl_xor_sync(0xffffffffu, q, off);
    }
    float mean = s * (1.f / 256.f);
    float var = q * (1.f / 256.f) - mean * mean;
    float inv = rsqrtf(var + 1e-5f);

    const float* gp = gamma + lane * 8;
    const float* bp = beta + lane * 8;
    float4 g0 = *(const float4*)gp, g1 = *(const float4*)(gp + 4);
    float4 b0 = *(const float4*)bp, b1 = *(const float4*)(bp + 4);
    float gg[8] = {g0.x, g0.y, g0.z, g0.w, g1.x, g1.y, g1.z, g1.w};
    float bbv[8] = {b0.x, b0.y, b0.z, b0.w, b1.x, b1.y, b1.z, b1.w};
    float o[8];
#pragma unroll
    for (int dd = 0; dd < 8; dd++) o[dd] = fmaf((v[dd] - mean) * inv, gg[dd], bbv[dd]);

    float* qo = out + (size_t)n * DDIM + lane * 8;
    *(float4*)qo       = make_float4(o[0], o[1], o[2], o[3]);
    *(float4*)(qo + 4) = make_float4(o[4], o[5], o[6], o[7]);
}

// ============================================================================
extern "C" void kernel_launch(void* const* d_in, const int* in_sizes, int n_in,
                              void* d_out, int out_size) {
    const float* zs    = (const float*)d_in[0];
    const float* Wb    = (const float*)d_in[1];
    const float* bb    = (const float*)d_in[2];
    const float* Wmax  = (const float*)d_in[3];
    const float* bmax  = (const float*)d_in[4];
    const float* Wphi  = (const float*)d_in[5];
    const float* bphi  = (const float*)d_in[6];
    const float* Wc    = (const float*)d_in[7];
    const float* bc    = (const float*)d_in[8];
    const float* gamma = (const float*)d_in[9];
    const float* beta  = (const float*)d_in[10];
    float* out = (float*)d_out;

    int N = in_sizes[0] / (MREL * DDIM);
    int nt128 = (N + 127) / 128;
    long long n4 = (long long)in_sizes[0] / 4;

    static cudaStream_t s1 = 0;
    static cudaEvent_t evf = 0, ev1 = 0;
    static int configured = 0;
    if (!configured) {
        cudaFuncSetAttribute(k_gate_logits, cudaFuncAttributeMaxDynamicSharedMemorySize, 71936);
        cudaFuncSetAttribute(k_maxphi_mma, cudaFuncAttributeMaxDynamicSharedMemorySize, 114688);
        cudaFuncSetAttribute(k_combine_mma, cudaFuncAttributeMaxDynamicSharedMemorySize, 88064);
        cudaStreamCreateWithFlags(&s1, cudaStreamNonBlocking);
        cudaEventCreateWithFlags(&evf, cudaEventDisableTiming);
        cudaEventCreateWithFlags(&ev1, cudaEventDisableTiming);
        configured = 1;
    }

    // fork s1 from the capture-origin stream FIRST (capture-legal topology)
    cudaEventRecord(evf, 0);
    cudaStreamWaitEvent(s1, evf, 0);

    // s1: gate pipeline (independent of s0's maxphi chain)
    k_wbtrans<<<8, 256, 0, s1>>>(Wb);
    k_gate_logits<<<nt128, 256, 71936, s1>>>(zs, bb, N);
    k_gate_zsum2<<<(N + 7) / 8, 256, 0, s1>>>(zs, N);
    cudaEventRecord(ev1, s1);

    // s0: fp16 conversion + weight transposes -> maxphi
    k_cvt_zs<<<2048, 256>>>(zs, n4);
    k_wtrans<<<dim3(8, 8, 16), 256>>>(Wmax, Wphi);
    k_wctrans<<<dim3(24, 8), 256>>>(Wc);
    k_maxphi_mma<<<dim3(4, nt128), 256, 114688>>>(bmax, bphi, N);

    // combine part B: k in [256, 768) -- depends only on maxphi outputs
    k_combine_mma<<<dim3(4, nt128), 256, 88064>>>(bc, N, 4, 12, 0);

    // join, then combine part A: k in [0, 256) (needs z_sum) + bias finalize
    cudaStreamWaitEvent(0, ev1, 0);
    k_combine_mma<<<dim3(4, nt128), 256, 88064>>>(bc, N, 0, 4, 1);

    k_ln<<<(N + 7) / 8, 256>>>(gamma, beta, out, N);
}